// round 12
// baseline (speedup 1.0000x reference)
#include <cuda_runtime.h>
#include <cstdint>

// Problem constants (B=64, C=512, H=W=28, G=8)
#define HWN    784
#define HW4    196
#define CPG    64
#define CPC    32        // channels per CTA (half group)
#define EPS    1e-5f
#define NTHR   256       // 8 warps
#define NTILE  512
#define NCL    74        // clusters (grid 148 / 2)
#define GRID   148

#define HALF_FLOATS (CPC * HWN)          // 25088
#define HALF_BYTES  (HALF_FLOATS * 4)    // 100352
#define TILE_FLOATS (CPG * HWN)          // 50176

// smem layout (floats): two half-tile buffers + s/gate + means + scratch + mbars
#define OFF_S      (2 * HALF_FLOATS)     // 50176
#define OFF_MEANS  (OFF_S + HWN)         // +784
#define OFF_RED    (OFF_MEANS + CPC)     // +32
#define OFF_MBAR   (OFF_RED + 20)        // even float offset -> 8B aligned
#define SMEM_FLOATS (OFF_MBAR + 4)       // 2 x u64 mbars
#define SMEM_BYTES  (SMEM_FLOATS * 4)    // ~199.3 KB -> 1 CTA/SM

__device__ __forceinline__ uint32_t smem_u32(const void* p) {
    uint32_t a;
    asm("{ .reg .u64 t; cvta.to.shared.u64 t, %1; cvt.u32.u64 %0, t; }"
        : "=r"(a) : "l"(p));
    return a;
}

__device__ __forceinline__ void cluster_sync_() {
    asm volatile("barrier.cluster.arrive.aligned;" ::: "memory");
    asm volatile("barrier.cluster.wait.aligned;" ::: "memory");
}

__device__ __forceinline__ void mbar_wait(uint32_t mbar, uint32_t parity) {
    asm volatile(
        "{\n\t"
        ".reg .pred P;\n\t"
        "WL_%=: mbarrier.try_wait.parity.acquire.cta.shared::cta.b64 P, [%0], %1, 0x989680;\n\t"
        "@P bra WD_%=;\n\t"
        "bra WL_%=;\n\t"
        "WD_%=:\n\t"
        "}" :: "r"(mbar), "r"(parity) : "memory");
}

__device__ __forceinline__ void tma_load_half(uint32_t mbar, uint32_t dst,
                                              const char* src) {
    asm volatile("mbarrier.arrive.expect_tx.shared::cta.b64 _, [%0], %1;"
                 :: "r"(mbar), "r"((uint32_t)HALF_BYTES) : "memory");
    asm volatile(
        "cp.async.bulk.shared::cluster.global.mbarrier::complete_tx::bytes "
        "[%0], [%1], %2, [%3];"
        :: "r"(dst), "l"(src), "r"((uint32_t)HALF_BYTES), "r"(mbar)
        : "memory");
}

__device__ __forceinline__ void tma_store_half(char* dstg, uint32_t src) {
    asm volatile(
        "cp.async.bulk.global.shared::cta.bulk_group [%0], [%1], %2;"
        :: "l"(dstg), "r"(src), "r"((uint32_t)HALF_BYTES) : "memory");
    asm volatile("cp.async.bulk.commit_group;" ::: "memory");
}

__global__ __launch_bounds__(NTHR, 1) __cluster_dims__(2, 1, 1)
void simam_pcl_kernel(const float* __restrict__ x,
                      const float* __restrict__ weight,
                      const float* __restrict__ bias,
                      float* __restrict__ out)
{
    extern __shared__ float smem[];
    float4* s_s4    = (float4*)(smem + OFF_S);     // partial s / gate (196 f4)
    float*  s_means = smem + OFF_MEANS;            // 32
    float*  s_red   = smem + OFF_RED;              // 18 used
    const uint32_t mbar0 = smem_u32(smem + OFF_MBAR);
    const uint32_t sx0   = smem_u32(smem);

    const int rank = (int)(blockIdx.x & 1);
    const int cl   = (int)(blockIdx.x >> 1);
    const size_t half_off = (size_t)rank * HALF_FLOATS;

    const int tid  = threadIdx.x;
    const int w    = tid >> 5;
    const int lane = tid & 31;

    // ---- init mbars + prologue: depth-2 lookahead ----
    if (tid == 0) {
        asm volatile("mbarrier.init.shared::cta.b64 [%0], 1;" :: "r"(mbar0)     : "memory");
        asm volatile("mbarrier.init.shared::cta.b64 [%0], 1;" :: "r"(mbar0 + 8) : "memory");
    }
    __syncthreads();
    if (tid == 0) {
        tma_load_half(mbar0, sx0,
                      (const char*)(x + (size_t)cl * TILE_FLOATS + half_off));
        const int t1 = cl + NCL;
        if (t1 < NTILE)
            tma_load_half(mbar0 + 8, sx0 + HALF_BYTES,
                          (const char*)(x + (size_t)t1 * TILE_FLOATS + half_off));
    }

    int it = 0;
    for (int tile = cl; tile < NTILE; tile += NCL, ++it) {
        const int      buf  = it & 1;
        const uint32_t par  = (uint32_t)((it >> 1) & 1);
        const int      g    = tile & 7;
        float* bufp = smem + buf * HALF_FLOATS;
        char*  ot   = (char*)(out + (size_t)tile * TILE_FLOATS + half_off);

        mbar_wait(mbar0 + buf * 8, par);

        // ---- per-channel means: 8 warps x 4 channels ----
        #pragma unroll
        for (int i = 0; i < 4; i++) {
            const int c = w + 8 * i;
            const float4* row = (const float4*)(bufp + c * HWN);
            float cs = 0.f;
            #pragma unroll
            for (int k = 0; k < 7; k++) {
                const int j = lane + 32 * k;
                if (j < HW4) {
                    float4 v = row[j];
                    cs += (v.x + v.y) + (v.z + v.w);
                }
            }
            #pragma unroll
            for (int o = 16; o; o >>= 1) cs += __shfl_xor_sync(0xffffffffu, cs, o);
            if (lane == 0) s_means[c] = cs * (1.0f / HWN);
        }
        __syncthreads();

        // ---- partial s over this CTA's 32 channels ----
        float4 acc = make_float4(0.f, 0.f, 0.f, 0.f);
        if (tid < HW4) {
            const float4* col = (const float4*)bufp + tid;
            #pragma unroll 8
            for (int c = 0; c < CPC; c++) {
                const float  m = s_means[c];
                const float4 v = col[c * HW4];
                acc.x += m * v.x;
                acc.y += m * v.y;
                acc.z += m * v.z;
                acc.w += m * v.w;
            }
            s_s4[tid] = acc;          // publish partial for peer
        }
        cluster_sync_();              // both partials published

        // ---- fetch peer partial via DSMEM ----
        float4 tot = acc;
        if (tid < HW4) {
            const uint32_t laddr = smem_u32(&s_s4[tid]);
            uint32_t raddr;
            asm("mapa.shared::cluster.u32 %0, %1, %2;"
                : "=r"(raddr) : "r"(laddr), "r"(rank ^ 1));
            float4 p;
            asm volatile("ld.shared::cluster.v4.f32 {%0,%1,%2,%3}, [%4];"
                         : "=f"(p.x), "=f"(p.y), "=f"(p.z), "=f"(p.w)
                         : "r"(raddr));
            tot.x += p.x; tot.y += p.y; tot.z += p.z; tot.w += p.w;
        }

        // ---- stats (redundant in both CTAs, deterministic) ----
        float lsum = 0.f, lsq = 0.f;
        if (tid < HW4) {
            lsum = (tot.x + tot.y) + (tot.z + tot.w);
            lsq  = tot.x * tot.x + tot.y * tot.y + tot.z * tot.z + tot.w * tot.w;
        }
        #pragma unroll
        for (int o = 16; o; o >>= 1) {
            lsum += __shfl_xor_sync(0xffffffffu, lsum, o);
            lsq  += __shfl_xor_sync(0xffffffffu, lsq,  o);
        }
        if (lane == 0) { s_red[w] = lsum; s_red[8 + w] = lsq; }
        __syncthreads();
        if (tid == 0) {
            float ts = 0.f, tq = 0.f;
            #pragma unroll
            for (int i = 0; i < 8; i++) { ts += s_red[i]; tq += s_red[8 + i]; }
            const float mu  = ts * (1.0f / HWN);
            const float var = tq * (1.0f / HWN) - mu * mu;
            s_red[16] = mu;
            s_red[17] = rsqrtf(var + EPS);
        }
        cluster_sync_();              // peer done reading our partial s

        // ---- gate into s buffer ----
        {
            const float mu = s_red[16];
            const float rs = s_red[17];
            const float wg = weight[g];
            const float bb = bias[g];
            if (tid < HW4) {
                float4 gt;
                gt.x = 1.0f / (1.0f + __expf(-((tot.x - mu) * rs * wg + bb)));
                gt.y = 1.0f / (1.0f + __expf(-((tot.y - mu) * rs * wg + bb)));
                gt.z = 1.0f / (1.0f + __expf(-((tot.z - mu) * rs * wg + bb)));
                gt.w = 1.0f / (1.0f + __expf(-((tot.w - mu) * rs * wg + bb)));
                s_s4[tid] = gt;
            }
        }
        __syncthreads();

        // ---- in-place multiply ----
        #pragma unroll
        for (int i = 0; i < 4; i++) {
            const int c = w + 8 * i;
            float4* row = (float4*)(bufp + c * HWN);
            #pragma unroll
            for (int k = 0; k < 7; k++) {
                const int j = lane + 32 * k;
                if (j < HW4) {
                    float4 v = row[j];
                    const float4 gt = s_s4[j];
                    v.x *= gt.x; v.y *= gt.y; v.z *= gt.z; v.w *= gt.w;
                    row[j] = v;
                }
            }
        }
        __syncthreads();

        // ---- TMA store this buffer; prefetch tile it+2 into it when free ----
        if (tid == 0) {
            asm volatile("fence.proxy.async.shared::cta;" ::: "memory");
            tma_store_half(ot, sx0 + buf * HALF_BYTES);
            const int tn = tile + 2 * NCL;
            if (tn < NTILE) {
                // wait until all committed stores (incl. this one) finished
                // reading smem, then reuse the buffer for the prefetch
                asm volatile("cp.async.bulk.wait_group.read 0;" ::: "memory");
                tma_load_half(mbar0 + buf * 8, sx0 + buf * HALF_BYTES,
                              (const char*)(x + (size_t)tn * TILE_FLOATS + half_off));
            }
        }
    }

    // drain outstanding bulk stores before exit
    if (tid == 0) {
        asm volatile("cp.async.bulk.wait_group 0;" ::: "memory");
    }
    __syncthreads();
}

extern "C" void kernel_launch(void* const* d_in, const int* in_sizes, int n_in,
                              void* d_out, int out_size)
{
    const float* x  = (const float*)d_in[0];
    const float* wt = (const float*)d_in[1];
    const float* bs = (const float*)d_in[2];
    float* out = (float*)d_out;

    cudaFuncSetAttribute(simam_pcl_kernel,
                         cudaFuncAttributeMaxDynamicSharedMemorySize, SMEM_BYTES);
    simam_pcl_kernel<<<GRID, NTHR, SMEM_BYTES>>>(x, wt, bs, out);
}